// round 10
// baseline (speedup 1.0000x reference)
#include <cuda_runtime.h>
#include <cuda_bf16.h>
#include <stdint.h>
#include <math.h>

#define T_STEPS 512
#define BATCH   32
#define HID     1024
#define INP     1024
#define G4H     4096

// ---------------- global scratch (no allocations allowed) ----------------
__device__ float g_xg[(size_t)T_STEPS * G4H * BATCH];   // [t][n][b]
// U packed in per-thread m16n8k16 A-fragment order, bf16 hi/lo:
// unit u (16B) = [jt(128)][w(8)][kt(8)][mt(2)][term(2)][lane(32)]
__device__ __align__(16) unsigned char g_Upk[128u * 8u * 1024u * 16u];   // 16 MB
// h packed in B-fragment order, bf16 hi/lo, double buffered on t&1:
// unit (8B) = [w(8)][kt(8)][nt(4)][term(2)][lane(32)]
__device__ __align__(16) unsigned char g_hpk[2][8u * 8u * 4u * 2u * 32u * 8u]; // 2 x 128KB
// x packed in A-fragment order: unit (16B) = [m16(1024)][kt(64)][term(2)][lane(32)]
__device__ __align__(16) unsigned char g_xpk[1024u * 64u * 2u * 32u * 16u];    // 64 MB
// W packed in B-fragment order: unit (8B) = [n8(512)][kt(64)][term(2)][lane(32)]
__device__ __align__(16) unsigned char g_Wpk[512u * 64u * 2u * 32u * 8u];      // 16 MB
// grid-barrier state (reset by pack_x_kernel block 0 each launch)
__device__ unsigned int g_bar_count;
__device__ unsigned int g_bar_gen;

__device__ __forceinline__ unsigned short bfh(float f) {
    return __bfloat16_as_ushort(__float2bfloat16(f));
}
__device__ __forceinline__ float bfr(float f) {   // residual after hi
    return f - __bfloat162float(__float2bfloat16(f));
}
__device__ __forceinline__ void mma16816(float* d, const uint32_t* a, const uint32_t* b) {
    asm volatile(
        "mma.sync.aligned.m16n8k16.row.col.f32.bf16.bf16.f32 "
        "{%0,%1,%2,%3}, {%4,%5,%6,%7}, {%8,%9}, {%0,%1,%2,%3};"
        : "+f"(d[0]), "+f"(d[1]), "+f"(d[2]), "+f"(d[3])
        : "r"(a[0]), "r"(a[1]), "r"(a[2]), "r"(a[3]), "r"(b[0]), "r"(b[1]));
}
// scoped memory-order primitives for the grid barrier
__device__ __forceinline__ unsigned atom_add_acqrel(unsigned* p, unsigned v) {
    unsigned old;
    asm volatile("atom.acq_rel.gpu.add.u32 %0, [%1], %2;" : "=r"(old) : "l"(p), "r"(v) : "memory");
    return old;
}
__device__ __forceinline__ void atom_add_rel(unsigned* p, unsigned v) {
    unsigned old;
    asm volatile("atom.release.gpu.add.u32 %0, [%1], %2;" : "=r"(old) : "l"(p), "r"(v) : "memory");
}
__device__ __forceinline__ unsigned ld_acq(unsigned* p) {
    unsigned v;
    asm volatile("ld.acquire.gpu.u32 %0, [%1];" : "=r"(v) : "l"(p) : "memory");
    return v;
}
// fast gates: __expf-based, graceful at extreme args, rel err ~1e-6
__device__ __forceinline__ float fsig(float x) {
    return __fdividef(1.f, 1.f + __expf(-x));
}
__device__ __forceinline__ float ftanh(float x) {
    return __fdividef(2.f, 1.f + __expf(-2.f * x)) - 1.f;
}

// ---------------------------------------------------------------------------
// Kernel 1a: pack x into bf16 hi/lo A-fragment-linear layout (one-time).
// Block 0 thread 0 also resets the grid-barrier counters for this launch.
// ---------------------------------------------------------------------------
__global__ void pack_x_kernel(const float* __restrict__ x) {
    if (blockIdx.x == 0 && threadIdx.x == 0) {
        g_bar_count = 0;
        g_bar_gen = 0;
    }
    unsigned u = blockIdx.x * blockDim.x + threadIdx.x;   // 4,194,304 units
    int lane = u & 31;
    int term = (u >> 5) & 1;
    int kt   = (u >> 6) & 63;
    int m16  = u >> 12;

    int m_lo = m16 * 16 + (lane >> 2);
    int c0   = kt * 16 + (lane & 3) * 2;

    float2 aL0 = *(const float2*)(x + (size_t)m_lo * INP + c0);
    float2 aL8 = *(const float2*)(x + (size_t)m_lo * INP + c0 + 8);
    float2 aH0 = *(const float2*)(x + (size_t)(m_lo + 8) * INP + c0);
    float2 aH8 = *(const float2*)(x + (size_t)(m_lo + 8) * INP + c0 + 8);

    if (term) {
        aL0.x = bfr(aL0.x); aL0.y = bfr(aL0.y); aL8.x = bfr(aL8.x); aL8.y = bfr(aL8.y);
        aH0.x = bfr(aH0.x); aH0.y = bfr(aH0.y); aH8.x = bfr(aH8.x); aH8.y = bfr(aH8.y);
    }
    uint4 q;
    q.x = (uint32_t)bfh(aL0.x) | ((uint32_t)bfh(aL0.y) << 16);
    q.y = (uint32_t)bfh(aH0.x) | ((uint32_t)bfh(aH0.y) << 16);
    q.z = (uint32_t)bfh(aL8.x) | ((uint32_t)bfh(aL8.y) << 16);
    q.w = (uint32_t)bfh(aH8.x) | ((uint32_t)bfh(aH8.y) << 16);
    ((uint4*)g_xpk)[u] = q;
}

// ---------------------------------------------------------------------------
// Kernel 1b: pack W into bf16 hi/lo B-fragment-linear layout (one-time).
// ---------------------------------------------------------------------------
__global__ void pack_W_kernel(const float* __restrict__ W) {
    unsigned u = blockIdx.x * blockDim.x + threadIdx.x;   // 2,097,152 units
    int lane = u & 31;
    int term = (u >> 5) & 1;
    int kt   = (u >> 6) & 63;
    int n8   = u >> 12;

    int n  = n8 * 8 + (lane >> 2);
    int k0 = kt * 16 + (lane & 3) * 2;

    float2 b0 = *(const float2*)(W + (size_t)n * INP + k0);
    float2 b1 = *(const float2*)(W + (size_t)n * INP + k0 + 8);
    if (term) { b0.x = bfr(b0.x); b0.y = bfr(b0.y); b1.x = bfr(b1.x); b1.y = bfr(b1.y); }
    uint2 q;
    q.x = (uint32_t)bfh(b0.x) | ((uint32_t)bfh(b0.y) << 16);
    q.y = (uint32_t)bfh(b1.x) | ((uint32_t)bfh(b1.y) << 16);
    ((uint2*)g_Wpk)[u] = q;
}

// ---------------------------------------------------------------------------
// Kernel 1c: xg = x @ W^T + bias via HMMA bf16-split, fragment-direct.
// Warp tile 64x64; epilogue adds bias, writes transposed [t][n][b].
// ---------------------------------------------------------------------------
__global__ void __launch_bounds__(256) gemm_xw_hmma(const float* __restrict__ bih,
                                                    const float* __restrict__ bhh) {
    const int w = threadIdx.x >> 5, lane = threadIdx.x & 31;
    const unsigned wtile = blockIdx.x * 8 + w;
    const int mtile = wtile >> 6;
    const int ntile = wtile & 63;

    float d[4][8][4] = {};
    const uint4* Xp = (const uint4*)g_xpk;
    const uint2* Wp = (const uint2*)g_Wpk;

    for (int kt = 0; kt < 64; kt++) {
        uint4 A[4][2];
#pragma unroll
        for (int mf = 0; mf < 4; mf++) {
            unsigned m16 = mtile * 4 + mf;
#pragma unroll
            for (int tm = 0; tm < 2; tm++)
                A[mf][tm] = Xp[(((m16 * 64u + kt) * 2u + tm) << 5) + lane];
        }
        uint2 Bv[8][2];
#pragma unroll
        for (int nf = 0; nf < 8; nf++) {
            unsigned n8 = ntile * 8 + nf;
#pragma unroll
            for (int tm = 0; tm < 2; tm++)
                Bv[nf][tm] = Wp[(((n8 * 64u + kt) * 2u + tm) << 5) + lane];
        }
#pragma unroll
        for (int mf = 0; mf < 4; mf++) {
#pragma unroll
            for (int nf = 0; nf < 8; nf++) {
                mma16816(d[mf][nf], (const uint32_t*)&A[mf][0], (const uint32_t*)&Bv[nf][0]);
                mma16816(d[mf][nf], (const uint32_t*)&A[mf][0], (const uint32_t*)&Bv[nf][1]);
                mma16816(d[mf][nf], (const uint32_t*)&A[mf][1], (const uint32_t*)&Bv[nf][0]);
            }
        }
    }

    const int g = lane >> 2, cb = (lane & 3) * 2;
#pragma unroll
    for (int nf = 0; nf < 8; nf++) {
        int n = ntile * 64 + nf * 8 + cb;
        float bs0 = bih[n] + bhh[n];
        float bs1 = bih[n + 1] + bhh[n + 1];
#pragma unroll
        for (int mf = 0; mf < 4; mf++) {
            int m0 = mtile * 64 + mf * 16 + g;
            int t0 = m0 >> 5, b0 = m0 & 31;
            int m1 = m0 + 8;
            int t1 = m1 >> 5, b1 = m1 & 31;
            float* p0 = g_xg + ((size_t)t0 * G4H + n) * BATCH + b0;
            float* p1 = g_xg + ((size_t)t1 * G4H + n) * BATCH + b1;
            p0[0]     = d[mf][nf][0] + bs0;
            p0[BATCH] = d[mf][nf][1] + bs1;
            p1[0]     = d[mf][nf][2] + bs0;
            p1[BATCH] = d[mf][nf][3] + bs1;
        }
    }
}

// ---------------------------------------------------------------------------
// Kernel 2: pack U into bf16 hi/lo m16n8k16 A-fragment-linear layout.
// ---------------------------------------------------------------------------
__global__ void pack_U_kernel(const float* __restrict__ U) {
    unsigned u = blockIdx.x * blockDim.x + threadIdx.x;   // 1,048,576 units
    int lane = u & 31;
    int term = (u >> 5) & 1;
    int mt   = (u >> 6) & 1;
    int kt   = (u >> 7) & 7;
    int w    = (u >> 10) & 7;
    int jt   = u >> 13;

    int r_lo = mt * 16 + (lane >> 2);
    int r_hi = r_lo + 8;
    int c0   = w * 128 + kt * 16 + (lane & 3) * 2;

    int R0 = (r_lo >> 3) * HID + jt * 8 + (r_lo & 7);
    int R1 = (r_hi >> 3) * HID + jt * 8 + (r_hi & 7);

    float2 aL0 = *(const float2*)(U + (size_t)R0 * INP + c0);
    float2 aL8 = *(const float2*)(U + (size_t)R0 * INP + c0 + 8);
    float2 aH0 = *(const float2*)(U + (size_t)R1 * INP + c0);
    float2 aH8 = *(const float2*)(U + (size_t)R1 * INP + c0 + 8);

    if (term) {
        aL0.x = bfr(aL0.x); aL0.y = bfr(aL0.y); aL8.x = bfr(aL8.x); aL8.y = bfr(aL8.y);
        aH0.x = bfr(aH0.x); aH0.y = bfr(aH0.y); aH8.x = bfr(aH8.x); aH8.y = bfr(aH8.y);
    }
    uint4 q;
    q.x = (uint32_t)bfh(aL0.x) | ((uint32_t)bfh(aL0.y) << 16);
    q.y = (uint32_t)bfh(aH0.x) | ((uint32_t)bfh(aH0.y) << 16);
    q.z = (uint32_t)bfh(aL8.x) | ((uint32_t)bfh(aL8.y) << 16);
    q.w = (uint32_t)bfh(aH8.x) | ((uint32_t)bfh(aH8.y) << 16);

    ((uint4*)g_Upk)[u] = q;
}

// ---------------------------------------------------------------------------
// Kernel 3: PERSISTENT recurrence v3. 128 CTAs x 256 thr; CTA jt owns 8 hidden
// cols x 4 gates (M=32). U fragments are LOOP-INVARIANT -> hoisted into 128
// registers per thread (one L2 read total instead of one per step, halving
// per-step L2 traffic). Register cell state, xg prefetch pre-barrier,
// acq/rel scoped barrier, fast gate math.
// ---------------------------------------------------------------------------
__global__ void __launch_bounds__(256, 1) lstm_persist(float* __restrict__ out) {
    __shared__ float Sp[8][32][36];   // per-warp partials
    __shared__ float S2[32][32];      // reduced S[m][b]
    __shared__ float Hs[8][33];       // h staging [jj][b]

    const int tid = threadIdx.x;
    const int w = tid >> 5, lane = tid & 31;
    const int jt = blockIdx.x, j0 = jt * 8;
    const size_t slab = (size_t)BATCH * HID;

    const int jj = tid >> 5, b = tid & 31;            // phase-1 (gates) mapping
    const int col = j0 + jj;
    const int g = lane >> 2, cb = (lane & 3) * 2;     // D-frag coords
    const int b2 = tid >> 3, j2 = tid & 7;            // phase-2 mapping

    // ---- hoist U A-fragments into registers (loop-invariant across t) ----
    const uint4* Ub = (const uint4*)g_Upk + ((size_t)(jt * 8 + w) << 10);
    uint4 Ureg[8][2][2];                               // [kt][mt][term] = 128 regs
#pragma unroll
    for (int kt = 0; kt < 8; kt++)
#pragma unroll
        for (int mt = 0; mt < 2; mt++)
#pragma unroll
            for (int tm = 0; tm < 2; tm++)
                Ureg[kt][mt][tm] = Ub[(((kt * 2 + mt) * 2 + tm) << 5) + lane];

    float creg = 0.f;                                  // cell state lives here
    // prefetch xg[0]
    float gi = g_xg[(size_t)(0 * HID + col) * BATCH + b];
    float gf = g_xg[(size_t)(1 * HID + col) * BATCH + b];
    float gc = g_xg[(size_t)(2 * HID + col) * BATCH + b];
    float go = g_xg[(size_t)(3 * HID + col) * BATCH + b];

    for (int t = 0; t < T_STEPS; t++) {
        if (t > 0) {
            float d[2][4][4] = {};
            const uint2* Hb = (const uint2*)g_hpk[(t & 1) ^ 1];
#pragma unroll
            for (int kt = 0; kt < 8; kt++) {
                uint2 Bv[4][2];
#pragma unroll
                for (int nt = 0; nt < 4; nt++)
#pragma unroll
                    for (int tm = 0; tm < 2; tm++)
                        Bv[nt][tm] = Hb[((((w * 8 + kt) * 4 + nt) * 2 + tm) << 5) + lane];
#pragma unroll
                for (int mt = 0; mt < 2; mt++)
#pragma unroll
                    for (int nt = 0; nt < 4; nt++) {
                        mma16816(d[mt][nt], (const uint32_t*)&Ureg[kt][mt][0], (const uint32_t*)&Bv[nt][0]);
                        mma16816(d[mt][nt], (const uint32_t*)&Ureg[kt][mt][0], (const uint32_t*)&Bv[nt][1]);
                        mma16816(d[mt][nt], (const uint32_t*)&Ureg[kt][mt][1], (const uint32_t*)&Bv[nt][0]);
                    }
            }
#pragma unroll
            for (int mt = 0; mt < 2; mt++)
#pragma unroll
                for (int nt = 0; nt < 4; nt++) {
                    int m = mt * 16 + g, n = nt * 8 + cb;
                    Sp[w][m][n]         = d[mt][nt][0];
                    Sp[w][m][n + 1]     = d[mt][nt][1];
                    Sp[w][m + 8][n]     = d[mt][nt][2];
                    Sp[w][m + 8][n + 1] = d[mt][nt][3];
                }
            __syncthreads();
            {   // reduce over 8 warps
                int m = tid >> 3, n4 = (tid & 7) * 4;
                float4 s = *(const float4*)&Sp[0][m][n4];
#pragma unroll
                for (int ww = 1; ww < 8; ww++) {
                    float4 p = *(const float4*)&Sp[ww][m][n4];
                    s.x += p.x; s.y += p.y; s.z += p.z; s.w += p.w;
                }
                *(float4*)&S2[m][n4] = s;
            }
            __syncthreads();
            gi += S2[0  + jj][b];
            gf += S2[8  + jj][b];
            gc += S2[16 + jj][b];
            go += S2[24 + jj][b];
        }

        // ---- gates + state update (fast math) ----
        {
            float it = fsig(gi);
            float ft = fsig(gf);
            float ch = ftanh(gc);
            float ot = fsig(go);
            creg = ft * creg + it * ch;
            Hs[jj][b] = ot * ftanh(creg);
        }
        __syncthreads();

        // ---- h output + B-fragment pack ----
        {
            float* hout = out + (size_t)t * slab;
            hout[(size_t)b2 * HID + j0 + j2] = Hs[j2][b2];

            int p = (tid >> 1) & 3, term = tid & 1;
            int c = j0 + 2 * p;
            float v0 = Hs[2 * p][b2], v1 = Hs[2 * p + 1][b2];
            if (term) { v0 = bfr(v0); v1 = bfr(v1); }
            uint32_t pk = (uint32_t)bfh(v0) | ((uint32_t)bfh(v1) << 16);
            int ww = c >> 7, kt = (c >> 4) & 7, nt = b2 >> 3;
            int tf = (b2 & 7) * 4 + ((c & 7) >> 1);
            int q  = (c >> 3) & 1;
            unsigned char* dst = g_hpk[t & 1] +
                ((size_t)((((ww * 8 + kt) * 4 + nt) * 2 + term) * 32 + tf) << 3) + q * 4;
            *(uint32_t*)dst = pk;
        }

        if (t + 1 < T_STEPS) {
            // ---- prefetch xg[t+1] BEFORE the barrier (read-only, race-free;
            //      DRAM latency overlaps the barrier wait) ----
            const float* xb = g_xg + (size_t)(t + 1) * G4H * BATCH;
            float ngi = xb[(size_t)(0 * HID + col) * BATCH + b];
            float ngf = xb[(size_t)(1 * HID + col) * BATCH + b];
            float ngc = xb[(size_t)(2 * HID + col) * BATCH + b];
            float ngo = xb[(size_t)(3 * HID + col) * BATCH + b];

            // ---- grid barrier: syncthreads publishes CTA writes, then scoped
            //      acq_rel arrival; last CTA releases the generation ----
            __syncthreads();
            if (tid == 0) {
                unsigned arr = atom_add_acqrel(&g_bar_count, 1u);
                if (arr == (unsigned)(t * 128 + 127))
                    atom_add_rel(&g_bar_gen, 1u);
                while (ld_acq(&g_bar_gen) < (unsigned)(t + 1)) { }
            }
            __syncthreads();

            gi = ngi; gf = ngf; gc = ngc; go = ngo;
        }
    }

    // ---- finalize: h_n (copy of out[T-1]) and c_n from register state ----
    out[(size_t)T_STEPS * slab + (size_t)b2 * HID + j0 + j2] = Hs[j2][b2];
    out[(size_t)(T_STEPS + 1) * slab + (size_t)b * HID + col] = creg;
}

extern "C" void kernel_launch(void* const* d_in, const int* in_sizes, int n_in,
                              void* d_out, int out_size) {
    const float* x   = (const float*)d_in[0];
    const float* W   = (const float*)d_in[1];
    const float* U   = (const float*)d_in[2];
    const float* bih = (const float*)d_in[3];
    const float* bhh = (const float*)d_in[4];
    float* out = (float*)d_out;

    pack_x_kernel<<<16384, 256>>>(x);
    pack_W_kernel<<<8192, 256>>>(W);
    pack_U_kernel<<<4096, 256>>>(U);

    gemm_xw_hmma<<<2048, 256>>>(bih, bhh);

    lstm_persist<<<128, 256>>>(out);
}

// round 11
// speedup vs baseline: 1.1335x; 1.1335x over previous
#include <cuda_runtime.h>
#include <cuda_bf16.h>
#include <stdint.h>
#include <math.h>

#define T_STEPS 512
#define BATCH   32
#define HID     1024
#define INP     1024
#define G4H     4096

// ---------------- global scratch (no allocations allowed) ----------------
__device__ float g_xg[(size_t)T_STEPS * G4H * BATCH];   // [t][n][b]
// U packed in per-thread m16n8k16 A-fragment order, bf16 hi/lo:
// unit u (16B) = [jt(128)][w(8)][kt(8)][mt(2)][term(2)][lane(32)]
__device__ __align__(16) unsigned char g_Upk[128u * 8u * 1024u * 16u];   // 16 MB
// h packed in B-fragment order, bf16 hi/lo, double buffered on t&1:
// unit (8B) = [w(8)][kt(8)][nt(4)][term(2)][lane(32)]
__device__ __align__(16) unsigned char g_hpk[2][8u * 8u * 4u * 2u * 32u * 8u]; // 2 x 128KB
// x packed in A-fragment order: unit (16B) = [m16(1024)][kt(64)][term(2)][lane(32)]
__device__ __align__(16) unsigned char g_xpk[1024u * 64u * 2u * 32u * 16u];    // 64 MB
// W packed in B-fragment order: unit (8B) = [n8(512)][kt(64)][term(2)][lane(32)]
__device__ __align__(16) unsigned char g_Wpk[512u * 64u * 2u * 32u * 8u];      // 16 MB
// grid-barrier state (reset by pack_x_kernel block 0 each launch)
__device__ unsigned int g_bar_count;
__device__ unsigned int g_bar_gen;

__device__ __forceinline__ unsigned short bfh(float f) {
    return __bfloat16_as_ushort(__float2bfloat16(f));
}
__device__ __forceinline__ float bfr(float f) {   // residual after hi
    return f - __bfloat162float(__float2bfloat16(f));
}
__device__ __forceinline__ void mma16816(float* d, const uint32_t* a, const uint32_t* b) {
    asm volatile(
        "mma.sync.aligned.m16n8k16.row.col.f32.bf16.bf16.f32 "
        "{%0,%1,%2,%3}, {%4,%5,%6,%7}, {%8,%9}, {%0,%1,%2,%3};"
        : "+f"(d[0]), "+f"(d[1]), "+f"(d[2]), "+f"(d[3])
        : "r"(a[0]), "r"(a[1]), "r"(a[2]), "r"(a[3]), "r"(b[0]), "r"(b[1]));
}
// scoped memory-order primitives for the grid barrier
__device__ __forceinline__ unsigned atom_add_acqrel(unsigned* p, unsigned v) {
    unsigned old;
    asm volatile("atom.acq_rel.gpu.add.u32 %0, [%1], %2;" : "=r"(old) : "l"(p), "r"(v) : "memory");
    return old;
}
__device__ __forceinline__ void atom_add_rel(unsigned* p, unsigned v) {
    unsigned old;
    asm volatile("atom.release.gpu.add.u32 %0, [%1], %2;" : "=r"(old) : "l"(p), "r"(v) : "memory");
}
__device__ __forceinline__ unsigned ld_acq(unsigned* p) {
    unsigned v;
    asm volatile("ld.acquire.gpu.u32 %0, [%1];" : "=r"(v) : "l"(p) : "memory");
    return v;
}
// streaming loads/stores: L2-only (no L1 allocate), so U stays L1-resident
__device__ __forceinline__ uint2 ldcg_u2(const uint2* p) {
    uint2 v;
    asm volatile("ld.global.cg.v2.u32 {%0,%1}, [%2];" : "=r"(v.x), "=r"(v.y) : "l"(p));
    return v;
}
__device__ __forceinline__ float ldcg_f(const float* p) {
    float v;
    asm volatile("ld.global.cg.f32 %0, [%1];" : "=f"(v) : "l"(p));
    return v;
}
__device__ __forceinline__ void stcg_f(float* p, float v) {
    asm volatile("st.global.cg.f32 [%0], %1;" :: "l"(p), "f"(v) : "memory");
}
__device__ __forceinline__ void stcg_u32(uint32_t* p, uint32_t v) {
    asm volatile("st.global.cg.u32 [%0], %1;" :: "l"(p), "r"(v) : "memory");
}
// fast gates: __expf-based, graceful at extreme args, rel err ~1e-6
__device__ __forceinline__ float fsig(float x) {
    return __fdividef(1.f, 1.f + __expf(-x));
}
__device__ __forceinline__ float ftanh(float x) {
    return __fdividef(2.f, 1.f + __expf(-2.f * x)) - 1.f;
}

// ---------------------------------------------------------------------------
// Kernel 1a: pack x into bf16 hi/lo A-fragment-linear layout (one-time).
// Block 0 thread 0 also resets the grid-barrier counters for this launch.
// ---------------------------------------------------------------------------
__global__ void pack_x_kernel(const float* __restrict__ x) {
    if (blockIdx.x == 0 && threadIdx.x == 0) {
        g_bar_count = 0;
        g_bar_gen = 0;
    }
    unsigned u = blockIdx.x * blockDim.x + threadIdx.x;   // 4,194,304 units
    int lane = u & 31;
    int term = (u >> 5) & 1;
    int kt   = (u >> 6) & 63;
    int m16  = u >> 12;

    int m_lo = m16 * 16 + (lane >> 2);
    int c0   = kt * 16 + (lane & 3) * 2;

    float2 aL0 = *(const float2*)(x + (size_t)m_lo * INP + c0);
    float2 aL8 = *(const float2*)(x + (size_t)m_lo * INP + c0 + 8);
    float2 aH0 = *(const float2*)(x + (size_t)(m_lo + 8) * INP + c0);
    float2 aH8 = *(const float2*)(x + (size_t)(m_lo + 8) * INP + c0 + 8);

    if (term) {
        aL0.x = bfr(aL0.x); aL0.y = bfr(aL0.y); aL8.x = bfr(aL8.x); aL8.y = bfr(aL8.y);
        aH0.x = bfr(aH0.x); aH0.y = bfr(aH0.y); aH8.x = bfr(aH8.x); aH8.y = bfr(aH8.y);
    }
    uint4 q;
    q.x = (uint32_t)bfh(aL0.x) | ((uint32_t)bfh(aL0.y) << 16);
    q.y = (uint32_t)bfh(aH0.x) | ((uint32_t)bfh(aH0.y) << 16);
    q.z = (uint32_t)bfh(aL8.x) | ((uint32_t)bfh(aL8.y) << 16);
    q.w = (uint32_t)bfh(aH8.x) | ((uint32_t)bfh(aH8.y) << 16);
    ((uint4*)g_xpk)[u] = q;
}

// ---------------------------------------------------------------------------
// Kernel 1b: pack W into bf16 hi/lo B-fragment-linear layout (one-time).
// ---------------------------------------------------------------------------
__global__ void pack_W_kernel(const float* __restrict__ W) {
    unsigned u = blockIdx.x * blockDim.x + threadIdx.x;   // 2,097,152 units
    int lane = u & 31;
    int term = (u >> 5) & 1;
    int kt   = (u >> 6) & 63;
    int n8   = u >> 12;

    int n  = n8 * 8 + (lane >> 2);
    int k0 = kt * 16 + (lane & 3) * 2;

    float2 b0 = *(const float2*)(W + (size_t)n * INP + k0);
    float2 b1 = *(const float2*)(W + (size_t)n * INP + k0 + 8);
    if (term) { b0.x = bfr(b0.x); b0.y = bfr(b0.y); b1.x = bfr(b1.x); b1.y = bfr(b1.y); }
    uint2 q;
    q.x = (uint32_t)bfh(b0.x) | ((uint32_t)bfh(b0.y) << 16);
    q.y = (uint32_t)bfh(b1.x) | ((uint32_t)bfh(b1.y) << 16);
    ((uint2*)g_Wpk)[u] = q;
}

// ---------------------------------------------------------------------------
// Kernel 1c: xg = x @ W^T + bias via HMMA bf16-split, fragment-direct.
// Warp tile 64x64; epilogue adds bias, writes transposed [t][n][b].
// ---------------------------------------------------------------------------
__global__ void __launch_bounds__(256) gemm_xw_hmma(const float* __restrict__ bih,
                                                    const float* __restrict__ bhh) {
    const int w = threadIdx.x >> 5, lane = threadIdx.x & 31;
    const unsigned wtile = blockIdx.x * 8 + w;
    const int mtile = wtile >> 6;
    const int ntile = wtile & 63;

    float d[4][8][4] = {};
    const uint4* Xp = (const uint4*)g_xpk;
    const uint2* Wp = (const uint2*)g_Wpk;

    for (int kt = 0; kt < 64; kt++) {
        uint4 A[4][2];
#pragma unroll
        for (int mf = 0; mf < 4; mf++) {
            unsigned m16 = mtile * 4 + mf;
#pragma unroll
            for (int tm = 0; tm < 2; tm++)
                A[mf][tm] = Xp[(((m16 * 64u + kt) * 2u + tm) << 5) + lane];
        }
        uint2 Bv[8][2];
#pragma unroll
        for (int nf = 0; nf < 8; nf++) {
            unsigned n8 = ntile * 8 + nf;
#pragma unroll
            for (int tm = 0; tm < 2; tm++)
                Bv[nf][tm] = Wp[(((n8 * 64u + kt) * 2u + tm) << 5) + lane];
        }
#pragma unroll
        for (int mf = 0; mf < 4; mf++) {
#pragma unroll
            for (int nf = 0; nf < 8; nf++) {
                mma16816(d[mf][nf], (const uint32_t*)&A[mf][0], (const uint32_t*)&Bv[nf][0]);
                mma16816(d[mf][nf], (const uint32_t*)&A[mf][0], (const uint32_t*)&Bv[nf][1]);
                mma16816(d[mf][nf], (const uint32_t*)&A[mf][1], (const uint32_t*)&Bv[nf][0]);
            }
        }
    }

    const int g = lane >> 2, cb = (lane & 3) * 2;
#pragma unroll
    for (int nf = 0; nf < 8; nf++) {
        int n = ntile * 64 + nf * 8 + cb;
        float bs0 = bih[n] + bhh[n];
        float bs1 = bih[n + 1] + bhh[n + 1];
#pragma unroll
        for (int mf = 0; mf < 4; mf++) {
            int m0 = mtile * 64 + mf * 16 + g;
            int t0 = m0 >> 5, b0 = m0 & 31;
            int m1 = m0 + 8;
            int t1 = m1 >> 5, b1 = m1 & 31;
            float* p0 = g_xg + ((size_t)t0 * G4H + n) * BATCH + b0;
            float* p1 = g_xg + ((size_t)t1 * G4H + n) * BATCH + b1;
            p0[0]     = d[mf][nf][0] + bs0;
            p0[BATCH] = d[mf][nf][1] + bs1;
            p1[0]     = d[mf][nf][2] + bs0;
            p1[BATCH] = d[mf][nf][3] + bs1;
        }
    }
}

// ---------------------------------------------------------------------------
// Kernel 2: pack U into bf16 hi/lo m16n8k16 A-fragment-linear layout.
// ---------------------------------------------------------------------------
__global__ void pack_U_kernel(const float* __restrict__ U) {
    unsigned u = blockIdx.x * blockDim.x + threadIdx.x;   // 1,048,576 units
    int lane = u & 31;
    int term = (u >> 5) & 1;
    int mt   = (u >> 6) & 1;
    int kt   = (u >> 7) & 7;
    int w    = (u >> 10) & 7;
    int jt   = u >> 13;

    int r_lo = mt * 16 + (lane >> 2);
    int r_hi = r_lo + 8;
    int c0   = w * 128 + kt * 16 + (lane & 3) * 2;

    int R0 = (r_lo >> 3) * HID + jt * 8 + (r_lo & 7);
    int R1 = (r_hi >> 3) * HID + jt * 8 + (r_hi & 7);

    float2 aL0 = *(const float2*)(U + (size_t)R0 * INP + c0);
    float2 aL8 = *(const float2*)(U + (size_t)R0 * INP + c0 + 8);
    float2 aH0 = *(const float2*)(U + (size_t)R1 * INP + c0);
    float2 aH8 = *(const float2*)(U + (size_t)R1 * INP + c0 + 8);

    if (term) {
        aL0.x = bfr(aL0.x); aL0.y = bfr(aL0.y); aL8.x = bfr(aL8.x); aL8.y = bfr(aL8.y);
        aH0.x = bfr(aH0.x); aH0.y = bfr(aH0.y); aH8.x = bfr(aH8.x); aH8.y = bfr(aH8.y);
    }
    uint4 q;
    q.x = (uint32_t)bfh(aL0.x) | ((uint32_t)bfh(aL0.y) << 16);
    q.y = (uint32_t)bfh(aH0.x) | ((uint32_t)bfh(aH0.y) << 16);
    q.z = (uint32_t)bfh(aL8.x) | ((uint32_t)bfh(aL8.y) << 16);
    q.w = (uint32_t)bfh(aH8.x) | ((uint32_t)bfh(aH8.y) << 16);

    ((uint4*)g_Upk)[u] = q;
}

// ---------------------------------------------------------------------------
// Kernel 3: PERSISTENT recurrence v4 (= v2 structure + cache steering).
// 128 CTAs x 256 thr; CTA jt owns 8 hidden cols x 4 gates (M=32).
// U fragment loads use default caching -> stay L1-resident across all steps;
// h/xg streaming traffic uses ld.cg/st.cg (L2-only) so it can't evict U.
// Register cell state, xg prefetch pre-barrier, acq/rel scoped barrier.
// ---------------------------------------------------------------------------
__global__ void __launch_bounds__(256) lstm_persist(float* __restrict__ out) {
    __shared__ float Sp[8][32][36];   // per-warp partials
    __shared__ float S2[32][32];      // reduced S[m][b]
    __shared__ float Hs[8][33];       // h staging [jj][b]

    const int tid = threadIdx.x;
    const int w = tid >> 5, lane = tid & 31;
    const int jt = blockIdx.x, j0 = jt * 8;
    const size_t slab = (size_t)BATCH * HID;

    const int jj = tid >> 5, b = tid & 31;            // phase-1 (gates) mapping
    const int col = j0 + jj;
    const int g = lane >> 2, cb = (lane & 3) * 2;     // D-frag coords
    const int b2 = tid >> 3, j2 = tid & 7;            // phase-2 mapping

    const uint4* Ub = (const uint4*)g_Upk + ((size_t)(jt * 8 + w) << 10);

    float creg = 0.f;                                  // cell state lives here
    // prefetch xg[0] (streaming -> cg)
    float gi = ldcg_f(&g_xg[(size_t)(0 * HID + col) * BATCH + b]);
    float gf = ldcg_f(&g_xg[(size_t)(1 * HID + col) * BATCH + b]);
    float gc = ldcg_f(&g_xg[(size_t)(2 * HID + col) * BATCH + b]);
    float go = ldcg_f(&g_xg[(size_t)(3 * HID + col) * BATCH + b]);

    for (int t = 0; t < T_STEPS; t++) {
        if (t > 0) {
            float d[2][4][4] = {};
            const uint2* Hb = (const uint2*)g_hpk[(t & 1) ^ 1];
#pragma unroll
            for (int kt = 0; kt < 8; kt++) {
                uint4 A[2][2];
#pragma unroll
                for (int mt = 0; mt < 2; mt++)
#pragma unroll
                    for (int tm = 0; tm < 2; tm++)
                        A[mt][tm] = Ub[(((kt * 2 + mt) * 2 + tm) << 5) + lane];   // default: L1-cached
                uint2 Bv[4][2];
#pragma unroll
                for (int nt = 0; nt < 4; nt++)
#pragma unroll
                    for (int tm = 0; tm < 2; tm++)
                        Bv[nt][tm] = ldcg_u2(&Hb[((((w * 8 + kt) * 4 + nt) * 2 + tm) << 5) + lane]);  // L2-only
#pragma unroll
                for (int mt = 0; mt < 2; mt++)
#pragma unroll
                    for (int nt = 0; nt < 4; nt++) {
                        mma16816(d[mt][nt], (const uint32_t*)&A[mt][0], (const uint32_t*)&Bv[nt][0]);
                        mma16816(d[mt][nt], (const uint32_t*)&A[mt][0], (const uint32_t*)&Bv[nt][1]);
                        mma16816(d[mt][nt], (const uint32_t*)&A[mt][1], (const uint32_t*)&Bv[nt][0]);
                    }
            }
#pragma unroll
            for (int mt = 0; mt < 2; mt++)
#pragma unroll
                for (int nt = 0; nt < 4; nt++) {
                    int m = mt * 16 + g, n = nt * 8 + cb;
                    *(float2*)&Sp[w][m][n]     = make_float2(d[mt][nt][0], d[mt][nt][1]);
                    *(float2*)&Sp[w][m + 8][n] = make_float2(d[mt][nt][2], d[mt][nt][3]);
                }
            __syncthreads();
            {   // reduce over 8 warps
                int m = tid >> 3, n4 = (tid & 7) * 4;
                float4 s = *(const float4*)&Sp[0][m][n4];
#pragma unroll
                for (int ww = 1; ww < 8; ww++) {
                    float4 p = *(const float4*)&Sp[ww][m][n4];
                    s.x += p.x; s.y += p.y; s.z += p.z; s.w += p.w;
                }
                *(float4*)&S2[m][n4] = s;
            }
            __syncthreads();
            gi += S2[0  + jj][b];
            gf += S2[8  + jj][b];
            gc += S2[16 + jj][b];
            go += S2[24 + jj][b];
        }

        // ---- gates + state update (fast math) ----
        {
            float it = fsig(gi);
            float ft = fsig(gf);
            float ch = ftanh(gc);
            float ot = fsig(go);
            creg = ft * creg + it * ch;
            Hs[jj][b] = ot * ftanh(creg);
        }
        __syncthreads();

        // ---- h output + B-fragment pack (streaming -> cg stores) ----
        {
            float* hout = out + (size_t)t * slab;
            stcg_f(&hout[(size_t)b2 * HID + j0 + j2], Hs[j2][b2]);

            int p = (tid >> 1) & 3, term = tid & 1;
            int c = j0 + 2 * p;
            float v0 = Hs[2 * p][b2], v1 = Hs[2 * p + 1][b2];
            if (term) { v0 = bfr(v0); v1 = bfr(v1); }
            uint32_t pk = (uint32_t)bfh(v0) | ((uint32_t)bfh(v1) << 16);
            int ww = c >> 7, kt = (c >> 4) & 7, nt = b2 >> 3;
            int tf = (b2 & 7) * 4 + ((c & 7) >> 1);
            int q  = (c >> 3) & 1;
            unsigned char* dst = g_hpk[t & 1] +
                ((size_t)((((ww * 8 + kt) * 4 + nt) * 2 + term) * 32 + tf) << 3) + q * 4;
            stcg_u32((uint32_t*)dst, pk);
        }

        if (t + 1 < T_STEPS) {
            // ---- prefetch xg[t+1] BEFORE the barrier (read-only, race-free;
            //      DRAM latency overlaps the barrier wait; cg keeps L1 clean) ----
            const float* xb = g_xg + (size_t)(t + 1) * G4H * BATCH;
            float ngi = ldcg_f(&xb[(size_t)(0 * HID + col) * BATCH + b]);
            float ngf = ldcg_f(&xb[(size_t)(1 * HID + col) * BATCH + b]);
            float ngc = ldcg_f(&xb[(size_t)(2 * HID + col) * BATCH + b]);
            float ngo = ldcg_f(&xb[(size_t)(3 * HID + col) * BATCH + b]);

            // ---- grid barrier: syncthreads publishes CTA writes, then scoped
            //      acq_rel arrival; last CTA releases the generation ----
            __syncthreads();
            if (tid == 0) {
                unsigned arr = atom_add_acqrel(&g_bar_count, 1u);
                if (arr == (unsigned)(t * 128 + 127))
                    atom_add_rel(&g_bar_gen, 1u);
                while (ld_acq(&g_bar_gen) < (unsigned)(t + 1)) { }
            }
            __syncthreads();

            gi = ngi; gf = ngf; gc = ngc; go = ngo;
        }
    }

    // ---- finalize: h_n (copy of out[T-1]) and c_n from register state ----
    out[(size_t)T_STEPS * slab + (size_t)b2 * HID + j0 + j2] = Hs[j2][b2];
    out[(size_t)(T_STEPS + 1) * slab + (size_t)b * HID + col] = creg;
}

extern "C" void kernel_launch(void* const* d_in, const int* in_sizes, int n_in,
                              void* d_out, int out_size) {
    const float* x   = (const float*)d_in[0];
    const float* W   = (const float*)d_in[1];
    const float* U   = (const float*)d_in[2];
    const float* bih = (const float*)d_in[3];
    const float* bhh = (const float*)d_in[4];
    float* out = (float*)d_out;

    pack_x_kernel<<<16384, 256>>>(x);
    pack_W_kernel<<<8192, 256>>>(W);
    pack_U_kernel<<<4096, 256>>>(U);

    gemm_xw_hmma<<<2048, 256>>>(bih, bhh);

    lstm_persist<<<128, 256>>>(out);
}